// round 7
// baseline (speedup 1.0000x reference)
#include <cuda_runtime.h>
#include <cstdint>
#include <cstddef>

// ----------------------------------------------------------------------------
// BlockCirculantLinear on GB300 (sm_103a; PTX target lacks 'a' => no tcgen05).
// FFT-domain formulation (8-pt rfft convolution theorem), legacy mma.sync tf32.
// R5: GEMM retiled BM=256 x BN=128 (512 thr) to cut L2->SM bytes/FLOP: demand
// 64 -> 48 B/cyc/SM vs ~42 B/cyc LTS cap, removing the L2 stretch seen in R4.
// ----------------------------------------------------------------------------

#define BM 256
#define BN 128
#define BK 32
#define NSTAGE 3
#define MDIM 8192
#define NB 512
#define THREADS 512

static constexpr int AK      = 4096;                 // g_X row stride
static constexpr int BK_ROW  = 1024;                 // g_B row stride
static constexpr size_t PLANE = (size_t)MDIM * NB;

static constexpr int A_TILE  = BM * BK * 4;              // 32768
static constexpr int B_TILE  = BN * BK * 4;              // 16384
static constexpr int STAGE_BYTES = A_TILE + B_TILE;      // 49152
static constexpr int SMEM_TOTAL  = NSTAGE * STAGE_BYTES; // 147456

__device__ float g_X[(size_t)MDIM * AK];            // freq-domain x (tf32)
__device__ float g_B[(size_t)8 * NB * BK_ROW];      // freq-domain weights
__device__ float g_O[(size_t)8 * PLANE];            // GEMM outputs

// ---------------- helpers ---------------------------------------------------

__device__ __forceinline__ uint32_t smem_u32(const void* p) {
    uint32_t a;
    asm("{ .reg .u64 t; cvta.to.shared.u64 t, %1; cvt.u32.u64 %0, t; }"
        : "=r"(a) : "l"(p));
    return a;
}

#define SWZ(off) ((off) ^ (((off) >> 3) & 0x70))

__device__ __forceinline__ void cp_async16(uint32_t dst, const float* src) {
    asm volatile("cp.async.cg.shared.global [%0], [%1], 16;" :: "r"(dst), "l"(src));
}
__device__ __forceinline__ void cp_commit() {
    asm volatile("cp.async.commit_group;" ::: "memory");
}
template <int N> __device__ __forceinline__ void cp_wait() {
    asm volatile("cp.async.wait_group %0;" :: "n"(N) : "memory");
}

__device__ __forceinline__ float tf32r(float x) {
    uint32_t u;
    asm("cvt.rna.tf32.f32 %0, %1;" : "=r"(u) : "f"(x));
    return __uint_as_float(u);
}

__device__ __forceinline__ void ldsm4(uint32_t* r, uint32_t addr) {
    asm volatile("ldmatrix.sync.aligned.m8n8.x4.shared.b16 {%0,%1,%2,%3}, [%4];"
                 : "=r"(r[0]), "=r"(r[1]), "=r"(r[2]), "=r"(r[3]) : "r"(addr));
}

__device__ __forceinline__ void mma_tf32(float* c, const uint32_t* a,
                                         uint32_t b0, uint32_t b1) {
    asm volatile(
        "mma.sync.aligned.m16n8k8.row.col.f32.tf32.tf32.f32 "
        "{%0,%1,%2,%3}, {%4,%5,%6,%7}, {%8,%9}, {%0,%1,%2,%3};"
        : "+f"(c[0]), "+f"(c[1]), "+f"(c[2]), "+f"(c[3])
        : "r"(a[0]), "r"(a[1]), "r"(a[2]), "r"(a[3]), "r"(b0), "r"(b1));
}

#define FFT8(x0,x1,x2,x3,x4,x5,x6,x7, R0,R4,R1,I1,R2,I2,R3,I3)                \
    {                                                                         \
        const float cc = 0.70710678118654752440f;                             \
        float s04 = (x0) + (x4), d04 = (x0) - (x4);                           \
        float s26 = (x2) + (x6), d26 = (x2) - (x6);                           \
        float s15 = (x1) + (x5), d15 = (x1) - (x5);                           \
        float s37 = (x3) + (x7), d37 = (x3) - (x7);                           \
        R0 = s04 + s26 + s15 + s37;                                           \
        R4 = s04 + s26 - s15 - s37;                                           \
        R2 = s04 - s26;                                                       \
        I2 = s37 - s15;                                                       \
        float e = cc * (d15 - d37), o = cc * (d15 + d37);                     \
        R1 = d04 + e;  I1 = -d26 - o;                                         \
        R3 = d04 - e;  I3 =  d26 - o;                                         \
    }

// ---------------- Kernel 1: x -> freq planes (tf32-rounded) -----------------
__global__ void fftx_kernel(const float4* __restrict__ x4) {
    int t  = blockIdx.x * blockDim.x + threadIdx.x;  // MDIM*NB
    int m  = t >> 9;
    int ib = t & 511;
    float4 a = x4[(size_t)m * 1024 + ib * 2];
    float4 b = x4[(size_t)m * 1024 + ib * 2 + 1];
    float R0, R4, R1, I1, R2, I2, R3, I3;
    FFT8(a.x, a.y, a.z, a.w, b.x, b.y, b.z, b.w, R0, R4, R1, I1, R2, I2, R3, I3);
    float* p = g_X + (size_t)m * AK + ib;
    p[0]    = tf32r(R0);
    p[512]  = tf32r(R4);
    p[1024] = tf32r(R1);
    p[1536] = tf32r(I1);
    p[2048] = tf32r(R2);
    p[2560] = tf32r(I2);
    p[3072] = tf32r(R3);
    p[3584] = tf32r(I3);
}

// ---------------- Kernel 2: circ -> freq weight job matrices ----------------
__global__ void fftc_kernel(const float* __restrict__ circ) {
    int t  = blockIdx.x * blockDim.x + threadIdx.x;  // NB*NB
    int nb = t >> 9;
    int ib = t & 511;
    const float* cp = circ + ((size_t)nb * NB + ib) * 8;
    float R0, R4, R1, I1, R2, I2, R3, I3;
    FFT8(cp[0], cp[1], cp[2], cp[3], cp[4], cp[5], cp[6], cp[7],
         R0, R4, R1, I1, R2, I2, R3, I3);
    R0 = tf32r(R0); R4 = tf32r(R4);
    R1 = tf32r(R1); I1 = tf32r(I1);
    R2 = tf32r(R2); I2 = tf32r(I2);
    R3 = tf32r(R3); I3 = tf32r(I3);
    const size_t JS = (size_t)NB * BK_ROW;
    float* r = g_B + (size_t)nb * BK_ROW + ib;
    r[0 * JS] = R0;
    r[1 * JS] = R4;
    r[2 * JS] = R1;  r[2 * JS + 512] = -I1;
    r[3 * JS] = I1;  r[3 * JS + 512] =  R1;
    r[4 * JS] = R2;  r[4 * JS + 512] = -I2;
    r[5 * JS] = I2;  r[5 * JS + 512] =  R2;
    r[6 * JS] = R3;  r[6 * JS + 512] = -I3;
    r[7 * JS] = I3;  r[7 * JS + 512] =  R3;
}

// ---------------- Kernel 3: batched TF32 mma.sync GEMM ----------------------
// 8 jobs x 32 m-tiles x 4 n-tiles. 16 warps as 4(m) x 4(n), warp tile 64x32.
__global__ void __launch_bounds__(THREADS) bc_gemm() {
    extern __shared__ char smem[];
    uint32_t sb0 = smem_u32(smem);
    const int tid = threadIdx.x;
    const int wid = tid >> 5;
    const int lid = tid & 31;
    const int wm = (wid >> 2) * 64;
    const int wn = (wid & 3) * 32;

    const int job = blockIdx.x >> 7;                 // 128 CTAs per job
    const int rem = blockIdx.x & 127;
    const int m0 = (rem & 31) * BM;
    const int n0 = (rem >> 5) * BN;
    const int NKIT = (job < 2) ? 16 : 32;            // K = 512 or 1024

    const float* Arow = g_X + (size_t)m0 * AK + (job >> 1) * 1024
                            + ((job == 1) ? 512 : 0);
    const float* Brow = g_B + (size_t)job * NB * BK_ROW + (size_t)n0 * BK_ROW;

    auto load_stage = [&](int s, int kiter) {
        uint32_t stg = sb0 + s * STAGE_BYTES;
        int k0 = kiter * BK;
#pragma unroll
        for (int q = 0; q < 4; q++) {                // A: 2048 chunks of 16B
            int idx = tid + q * THREADS;
            int row = idx >> 3;
            int ch  = idx & 7;
            uint32_t sw = SWZ((uint32_t)(row * 128 + ch * 16));
            cp_async16(stg + sw, Arow + (size_t)row * AK + k0 + ch * 4);
        }
#pragma unroll
        for (int q = 0; q < 2; q++) {                // B: 1024 chunks of 16B
            int idx = tid + q * THREADS;
            int row = idx >> 3;
            int ch  = idx & 7;
            uint32_t sw = SWZ((uint32_t)(row * 128 + ch * 16));
            cp_async16(stg + A_TILE + sw, Brow + (size_t)row * BK_ROW + k0 + ch * 4);
        }
        cp_commit();
    };

    float acc[4][4][4];
#pragma unroll
    for (int mf = 0; mf < 4; mf++)
#pragma unroll
        for (int nf = 0; nf < 4; nf++)
#pragma unroll
            for (int r = 0; r < 4; r++) acc[mf][nf][r] = 0.0f;

    load_stage(0, 0);
    load_stage(1, 1);

    const int lrow = lid & 15;
    const int lcol = (lid >> 4) * 16;

    for (int i = 0; i < NKIT; i++) {
        cp_wait<1>();
        __syncthreads();
        if (i + 2 < NKIT) load_stage((i + 2) % NSTAGE, i + 2);

        uint32_t Ab = sb0 + (i % NSTAGE) * STAGE_BYTES;
        uint32_t Bb = Ab + A_TILE;

#pragma unroll
        for (int ks = 0; ks < 4; ks++) {
            uint32_t a[4][4];
#pragma unroll
            for (int mf = 0; mf < 4; mf++) {
                uint32_t off = (uint32_t)((wm + mf * 16 + lrow) * 128 + ks * 32 + lcol);
                ldsm4(a[mf], Ab + SWZ(off));
            }
            uint32_t b[2][4];
#pragma unroll
            for (int p = 0; p < 2; p++) {
                uint32_t off = (uint32_t)((wn + p * 16 + lrow) * 128 + ks * 32 + lcol);
                ldsm4(b[p], Bb + SWZ(off));
            }
#pragma unroll
            for (int mf = 0; mf < 4; mf++)
#pragma unroll
                for (int nf = 0; nf < 4; nf++) {
                    int p = nf >> 1, o = nf & 1;
                    mma_tf32(acc[mf][nf], a[mf], b[p][o], b[p][2 + o]);
                }
        }
    }

    float* O = g_O + (size_t)job * PLANE;
    const int crow = lid >> 2;
    const int ccol = 2 * (lid & 3);
#pragma unroll
    for (int nf = 0; nf < 4; nf++) {
        int col = n0 + wn + nf * 8 + ccol;
#pragma unroll
        for (int mf = 0; mf < 4; mf++) {
            int row = m0 + wm + mf * 16 + crow;
            *(float2*)(O + (size_t)row * NB + col) =
                make_float2(acc[mf][nf][0], acc[mf][nf][1]);
            *(float2*)(O + (size_t)(row + 8) * NB + col) =
                make_float2(acc[mf][nf][2], acc[mf][nf][3]);
        }
    }
}

// ---------------- Kernel 4: inverse 8-pt rfft + bias ------------------------
__global__ void ifft_kernel(const float* __restrict__ bias,
                            float* __restrict__ out) {
    int t  = blockIdx.x * blockDim.x + threadIdx.x;  // MDIM*NB
    int m  = t >> 9;
    int nb = t & 511;
    const float* p = g_O + (size_t)m * NB + nb;
    float R0 = p[0 * PLANE], R4 = p[1 * PLANE];
    float R1 = p[2 * PLANE], I1 = p[3 * PLANE];
    float R2 = p[4 * PLANE], I2 = p[5 * PLANE];
    float R3 = p[6 * PLANE], I3 = p[7 * PLANE];

    const float cc = 0.70710678118654752440f;
    float se = R0 + R4, so = R0 - R4;
    float y0 = se + 2.0f * ( R1 + R2 + R3);
    float y2 = se + 2.0f * (-I1 - R2 + I3);
    float y4 = se + 2.0f * (-R1 + R2 - R3);
    float y6 = se + 2.0f * ( I1 - R2 - I3);
    float a1 = cc * (R1 - I1), b1 = cc * (R1 + I1);
    float a3 = cc * (R3 - I3), b3 = cc * (R3 + I3);
    float y1 = so + 2.0f * ( a1 - I2 - b3);
    float y3 = so + 2.0f * (-b1 + I2 + a3);
    float y5 = so + 2.0f * (-a1 - I2 + b3);
    float y7 = so + 2.0f * ( b1 + I2 - a3);

    const float4 bv0 = *(const float4*)(bias + nb * 8);
    const float4 bv1 = *(const float4*)(bias + nb * 8 + 4);
    float4* dst = (float4*)(out + (size_t)m * 4096 + nb * 8);
    dst[0] = make_float4(0.125f * y0 + bv0.x, 0.125f * y1 + bv0.y,
                         0.125f * y2 + bv0.z, 0.125f * y3 + bv0.w);
    dst[1] = make_float4(0.125f * y4 + bv1.x, 0.125f * y5 + bv1.y,
                         0.125f * y6 + bv1.z, 0.125f * y7 + bv1.w);
}

// ---------------- Launch ----------------------------------------------------

extern "C" void kernel_launch(void* const* d_in, const int* in_sizes, int n_in,
                              void* d_out, int out_size) {
    const float* x    = (const float*)d_in[0];
    const float* circ = (const float*)d_in[1];
    const float* bias = (const float*)d_in[2];
    float* out = (float*)d_out;

    fftx_kernel<<<(MDIM * NB) / 256, 256>>>((const float4*)x);
    fftc_kernel<<<(NB * NB) / 256, 256>>>(circ);

    cudaFuncSetAttribute(bc_gemm, cudaFuncAttributeMaxDynamicSharedMemorySize,
                         SMEM_TOTAL);
    bc_gemm<<<8 * 32 * 4, THREADS, SMEM_TOTAL>>>();   // 1024 CTAs

    ifft_kernel<<<(MDIM * NB) / 256, 256>>>(bias, out);
    (void)in_sizes; (void)n_in; (void)out_size;
}

// round 8
// speedup vs baseline: 1.2424x; 1.2424x over previous
#include <cuda_runtime.h>
#include <cuda_fp16.h>
#include <cstdint>
#include <cstddef>

// ----------------------------------------------------------------------------
// BlockCirculantLinear on GB300 (sm_103a; PTX target lacks 'a' => no tcgen05).
// FFT-domain formulation (8-pt rfft convolution theorem).
// R6: fp16 mma.sync m16n8k16 (same 10-bit mantissa as tf32 => same rounding
// error) halves HMMA count vs R4; fp16 tiles halve smem/LDSM/cp.async traffic.
// Tiling reverted to R4's proven 128x128x(BK=64), 256 thr, 2 CTAs/SM.
// ----------------------------------------------------------------------------

#define BM 128
#define BN 128
#define BK 64
#define NSTAGE 3
#define MDIM 8192
#define NB 512
#define THREADS 256

static constexpr int AK      = 4096;                 // g_X row stride (halves)
static constexpr int BK_ROW  = 1024;                 // g_B row stride (halves)
static constexpr size_t PLANE = (size_t)MDIM * NB;

static constexpr int TILE_BYTES  = BM * BK * 2;          // 16384 (fp16)
static constexpr int STAGE_BYTES = 2 * TILE_BYTES;       // 32768
static constexpr int SMEM_TOTAL  = NSTAGE * STAGE_BYTES; // 98304 -> 2 CTAs/SM

__device__ __half g_X[(size_t)MDIM * AK];           // freq-domain x (fp16)
__device__ __half g_B[(size_t)8 * NB * BK_ROW];     // freq-domain weights (fp16)
__device__ float  g_O[(size_t)8 * PLANE];           // GEMM outputs (fp32)

// ---------------- helpers ---------------------------------------------------

__device__ __forceinline__ uint32_t smem_u32(const void* p) {
    uint32_t a;
    asm("{ .reg .u64 t; cvta.to.shared.u64 t, %1; cvt.u32.u64 %0, t; }"
        : "=r"(a) : "l"(p));
    return a;
}

#define SWZ(off) ((off) ^ (((off) >> 3) & 0x70))

__device__ __forceinline__ void cp_async16(uint32_t dst, const void* src) {
    asm volatile("cp.async.cg.shared.global [%0], [%1], 16;" :: "r"(dst), "l"(src));
}
__device__ __forceinline__ void cp_commit() {
    asm volatile("cp.async.commit_group;" ::: "memory");
}
template <int N> __device__ __forceinline__ void cp_wait() {
    asm volatile("cp.async.wait_group %0;" :: "n"(N) : "memory");
}

__device__ __forceinline__ void ldsm4(uint32_t* r, uint32_t addr) {
    asm volatile("ldmatrix.sync.aligned.m8n8.x4.shared.b16 {%0,%1,%2,%3}, [%4];"
                 : "=r"(r[0]), "=r"(r[1]), "=r"(r[2]), "=r"(r[3]) : "r"(addr));
}

__device__ __forceinline__ void mma_f16(float* c, const uint32_t* a,
                                        uint32_t b0, uint32_t b1) {
    asm volatile(
        "mma.sync.aligned.m16n8k16.row.col.f32.f16.f16.f32 "
        "{%0,%1,%2,%3}, {%4,%5,%6,%7}, {%8,%9}, {%0,%1,%2,%3};"
        : "+f"(c[0]), "+f"(c[1]), "+f"(c[2]), "+f"(c[3])
        : "r"(a[0]), "r"(a[1]), "r"(a[2]), "r"(a[3]), "r"(b0), "r"(b1));
}

#define FFT8(x0,x1,x2,x3,x4,x5,x6,x7, R0,R4,R1,I1,R2,I2,R3,I3)                \
    {                                                                         \
        const float cc = 0.70710678118654752440f;                             \
        float s04 = (x0) + (x4), d04 = (x0) - (x4);                           \
        float s26 = (x2) + (x6), d26 = (x2) - (x6);                           \
        float s15 = (x1) + (x5), d15 = (x1) - (x5);                           \
        float s37 = (x3) + (x7), d37 = (x3) - (x7);                           \
        R0 = s04 + s26 + s15 + s37;                                           \
        R4 = s04 + s26 - s15 - s37;                                           \
        R2 = s04 - s26;                                                       \
        I2 = s37 - s15;                                                       \
        float e = cc * (d15 - d37), o = cc * (d15 + d37);                     \
        R1 = d04 + e;  I1 = -d26 - o;                                         \
        R3 = d04 - e;  I3 =  d26 - o;                                         \
    }

// ---------------- Kernel 1: x -> freq planes (fp16) -------------------------
__global__ void fftx_kernel(const float4* __restrict__ x4) {
    int t  = blockIdx.x * blockDim.x + threadIdx.x;  // MDIM*NB
    int m  = t >> 9;
    int ib = t & 511;
    float4 a = x4[(size_t)m * 1024 + ib * 2];
    float4 b = x4[(size_t)m * 1024 + ib * 2 + 1];
    float R0, R4, R1, I1, R2, I2, R3, I3;
    FFT8(a.x, a.y, a.z, a.w, b.x, b.y, b.z, b.w, R0, R4, R1, I1, R2, I2, R3, I3);
    __half* p = g_X + (size_t)m * AK + ib;
    p[0]    = __float2half_rn(R0);
    p[512]  = __float2half_rn(R4);
    p[1024] = __float2half_rn(R1);
    p[1536] = __float2half_rn(I1);
    p[2048] = __float2half_rn(R2);
    p[2560] = __float2half_rn(I2);
    p[3072] = __float2half_rn(R3);
    p[3584] = __float2half_rn(I3);
}

// ---------------- Kernel 2: circ -> freq weight job matrices (fp16) ---------
__global__ void fftc_kernel(const float* __restrict__ circ) {
    int t  = blockIdx.x * blockDim.x + threadIdx.x;  // NB*NB
    int nb = t >> 9;
    int ib = t & 511;
    const float* cp = circ + ((size_t)nb * NB + ib) * 8;
    float R0, R4, R1, I1, R2, I2, R3, I3;
    FFT8(cp[0], cp[1], cp[2], cp[3], cp[4], cp[5], cp[6], cp[7],
         R0, R4, R1, I1, R2, I2, R3, I3);
    const size_t JS = (size_t)NB * BK_ROW;
    __half* r = g_B + (size_t)nb * BK_ROW + ib;
    r[0 * JS] = __float2half_rn(R0);
    r[1 * JS] = __float2half_rn(R4);
    r[2 * JS] = __float2half_rn(R1);  r[2 * JS + 512] = __float2half_rn(-I1);
    r[3 * JS] = __float2half_rn(I1);  r[3 * JS + 512] = __float2half_rn( R1);
    r[4 * JS] = __float2half_rn(R2);  r[4 * JS + 512] = __float2half_rn(-I2);
    r[5 * JS] = __float2half_rn(I2);  r[5 * JS + 512] = __float2half_rn( R2);
    r[6 * JS] = __float2half_rn(R3);  r[6 * JS + 512] = __float2half_rn(-I3);
    r[7 * JS] = __float2half_rn(I3);  r[7 * JS + 512] = __float2half_rn( R3);
}

// ---------------- Kernel 3: batched FP16 mma.sync GEMM ----------------------
// 8 jobs x 64 m-tiles x 4 n-tiles. 8 warps as 2(m) x 4(n), warp tile 64x32.
__global__ void __launch_bounds__(THREADS) bc_gemm() {
    extern __shared__ char smem[];
    uint32_t sb0 = smem_u32(smem);
    const int tid = threadIdx.x;
    const int wid = tid >> 5;
    const int lid = tid & 31;
    const int wm = (wid >> 2) * 64;
    const int wn = (wid & 3) * 32;

    const int job = blockIdx.x >> 8;                 // 256 CTAs per job
    const int rem = blockIdx.x & 255;
    const int m0 = (rem & 63) * BM;
    const int n0 = (rem >> 6) * BN;
    const int NKIT = (job < 2) ? 8 : 16;             // K = 512 or 1024, BK=64

    const __half* Arow = g_X + (size_t)m0 * AK + (job >> 1) * 1024
                             + ((job == 1) ? 512 : 0);
    const __half* Brow = g_B + (size_t)job * NB * BK_ROW + (size_t)n0 * BK_ROW;

    // Stage: A 128x64 fp16 (128B rows, SW128) + B 128x64 fp16.
    auto load_stage = [&](int s, int kiter) {
        uint32_t stg = sb0 + s * STAGE_BYTES;
        int k0 = kiter * BK;
#pragma unroll
        for (int q = 0; q < 4; q++) {
            int idx = tid + q * THREADS;             // 0..1023 chunks of 16B
            int row = idx >> 3;
            int ch  = idx & 7;
            uint32_t sw = SWZ((uint32_t)(row * 128 + ch * 16));
            cp_async16(stg + sw,              Arow + (size_t)row * AK     + k0 + ch * 8);
            cp_async16(stg + TILE_BYTES + sw, Brow + (size_t)row * BK_ROW + k0 + ch * 8);
        }
        cp_commit();
    };

    float acc[4][4][4];
#pragma unroll
    for (int mf = 0; mf < 4; mf++)
#pragma unroll
        for (int nf = 0; nf < 4; nf++)
#pragma unroll
            for (int r = 0; r < 4; r++) acc[mf][nf][r] = 0.0f;

    load_stage(0, 0);
    load_stage(1, 1);

    const int lrow = lid & 15;
    const int lcol = (lid >> 4) * 16;   // 16B half-select within 32B k16 window

    for (int i = 0; i < NKIT; i++) {
        cp_wait<1>();
        __syncthreads();
        if (i + 2 < NKIT) load_stage((i + 2) % NSTAGE, i + 2);

        uint32_t Ab = sb0 + (i % NSTAGE) * STAGE_BYTES;
        uint32_t Bb = Ab + TILE_BYTES;

#pragma unroll
        for (int ks = 0; ks < 4; ks++) {             // 4 x k16 = BK 64
            uint32_t a[4][4];
#pragma unroll
            for (int mf = 0; mf < 4; mf++) {
                uint32_t off = (uint32_t)((wm + mf * 16 + lrow) * 128 + ks * 32 + lcol);
                ldsm4(a[mf], Ab + SWZ(off));
            }
            uint32_t b[2][4];   // [n16 group][r0=b0 lo, r1=b0 hi, r2=b1 lo, r3=b1 hi]
#pragma unroll
            for (int p = 0; p < 2; p++) {
                uint32_t off = (uint32_t)((wn + p * 16 + lrow) * 128 + ks * 32 + lcol);
                ldsm4(b[p], Bb + SWZ(off));
            }
#pragma unroll
            for (int mf = 0; mf < 4; mf++)
#pragma unroll
                for (int nf = 0; nf < 4; nf++) {
                    int p = nf >> 1, o = nf & 1;
                    mma_f16(acc[mf][nf], a[mf], b[p][o], b[p][2 + o]);
                }
        }
    }

    float* O = g_O + (size_t)job * PLANE;
    const int crow = lid >> 2;
    const int ccol = 2 * (lid & 3);
#pragma unroll
    for (int nf = 0; nf < 4; nf++) {
        int col = n0 + wn + nf * 8 + ccol;
#pragma unroll
        for (int mf = 0; mf < 4; mf++) {
            int row = m0 + wm + mf * 16 + crow;
            *(float2*)(O + (size_t)row * NB + col) =
                make_float2(acc[mf][nf][0], acc[mf][nf][1]);
            *(float2*)(O + (size_t)(row + 8) * NB + col) =
                make_float2(acc[mf][nf][2], acc[mf][nf][3]);
        }
    }
}

// ---------------- Kernel 4: inverse 8-pt rfft + bias ------------------------
__global__ void ifft_kernel(const float* __restrict__ bias,
                            float* __restrict__ out) {
    int t  = blockIdx.x * blockDim.x + threadIdx.x;  // MDIM*NB
    int m  = t >> 9;
    int nb = t & 511;
    const float* p = g_O + (size_t)m * NB + nb;
    float R0 = p[0 * PLANE], R4 = p[1 * PLANE];
    float R1 = p[2 * PLANE], I1 = p[3 * PLANE];
    float R2 = p[4 * PLANE], I2 = p[5 * PLANE];
    float R3 = p[6 * PLANE], I3 = p[7 * PLANE];

    const float cc = 0.70710678118654752440f;
    float se = R0 + R4, so = R0 - R4;
    float y0 = se + 2.0f * ( R1 + R2 + R3);
    float y2 = se + 2.0f * (-I1 - R2 + I3);
    float y4 = se + 2.0f * (-R1 + R2 - R3);
    float y6 = se + 2.0f * ( I1 - R2 - I3);
    float a1 = cc * (R1 - I1), b1 = cc * (R1 + I1);
    float a3 = cc * (R3 - I3), b3 = cc * (R3 + I3);
    float y1 = so + 2.0f * ( a1 - I2 - b3);
    float y3 = so + 2.0f * (-b1 + I2 + a3);
    float y5 = so + 2.0f * (-a1 - I2 + b3);
    float y7 = so + 2.0f * ( b1 + I2 - a3);

    const float4 bv0 = *(const float4*)(bias + nb * 8);
    const float4 bv1 = *(const float4*)(bias + nb * 8 + 4);
    float4* dst = (float4*)(out + (size_t)m * 4096 + nb * 8);
    dst[0] = make_float4(0.125f * y0 + bv0.x, 0.125f * y1 + bv0.y,
                         0.125f * y2 + bv0.z, 0.125f * y3 + bv0.w);
    dst[1] = make_float4(0.125f * y4 + bv1.x, 0.125f * y5 + bv1.y,
                         0.125f * y6 + bv1.z, 0.125f * y7 + bv1.w);
}

// ---------------- Launch ----------------------------------------------------

extern "C" void kernel_launch(void* const* d_in, const int* in_sizes, int n_in,
                              void* d_out, int out_size) {
    const float* x    = (const float*)d_in[0];
    const float* circ = (const float*)d_in[1];
    const float* bias = (const float*)d_in[2];
    float* out = (float*)d_out;

    fftx_kernel<<<(MDIM * NB) / 256, 256>>>((const float4*)x);
    fftc_kernel<<<(NB * NB) / 256, 256>>>(circ);

    cudaFuncSetAttribute(bc_gemm, cudaFuncAttributeMaxDynamicSharedMemorySize,
                         SMEM_TOTAL);
    bc_gemm<<<8 * 64 * 4, THREADS, SMEM_TOTAL>>>();   // 2048 CTAs

    ifft_kernel<<<(MDIM * NB) / 256, 256>>>(bias, out);
    (void)in_sizes; (void)n_in; (void)out_size;
}

// round 10
// speedup vs baseline: 1.8184x; 1.4636x over previous
#include <cuda_runtime.h>
#include <cuda_fp16.h>
#include <cstdint>
#include <cstddef>

// ----------------------------------------------------------------------------
// BlockCirculantLinear on GB300 (sm_103a; PTX target lacks 'a' => no tcgen05).
// FFT-domain formulation (8-pt rfft convolution theorem), fp16 mma.sync.
// R7: fp16 frequency-plane tensor g_O (halves epilogue+ifft traffic); irfft
// scale factors folded into the weight FFT (jobs 0,1: x1/8; AC jobs: x1/4).
// ----------------------------------------------------------------------------

#define BM 128
#define BN 128
#define BK 64
#define NSTAGE 3
#define MDIM 8192
#define NB 512
#define THREADS 256

static constexpr int AK      = 4096;                 // g_X row stride
static constexpr int BK_ROW  = 1024;                 // g_B row stride
static constexpr size_t PLANE = (size_t)MDIM * NB;

static constexpr int TILE_BYTES  = BM * BK * 2;          // 16384 (fp16)
static constexpr int STAGE_BYTES = 2 * TILE_BYTES;       // 32768
static constexpr int SMEM_TOTAL  = NSTAGE * STAGE_BYTES; // 98304 -> 2 CTAs/SM

__device__ __half g_X[(size_t)MDIM * AK];           // freq-domain x (fp16)
__device__ __half g_B[(size_t)8 * NB * BK_ROW];     // freq weights (fp16, scaled)
__device__ __half g_O[(size_t)8 * PLANE];           // freq planes (fp16)

// ---------------- helpers ---------------------------------------------------

__device__ __forceinline__ uint32_t smem_u32(const void* p) {
    uint32_t a;
    asm("{ .reg .u64 t; cvta.to.shared.u64 t, %1; cvt.u32.u64 %0, t; }"
        : "=r"(a) : "l"(p));
    return a;
}

#define SWZ(off) ((off) ^ (((off) >> 3) & 0x70))

__device__ __forceinline__ void cp_async16(uint32_t dst, const void* src) {
    asm volatile("cp.async.cg.shared.global [%0], [%1], 16;" :: "r"(dst), "l"(src));
}
__device__ __forceinline__ void cp_commit() {
    asm volatile("cp.async.commit_group;" ::: "memory");
}
template <int N> __device__ __forceinline__ void cp_wait() {
    asm volatile("cp.async.wait_group %0;" :: "n"(N) : "memory");
}

__device__ __forceinline__ void ldsm4(uint32_t* r, uint32_t addr) {
    asm volatile("ldmatrix.sync.aligned.m8n8.x4.shared.b16 {%0,%1,%2,%3}, [%4];"
                 : "=r"(r[0]), "=r"(r[1]), "=r"(r[2]), "=r"(r[3]) : "r"(addr));
}

__device__ __forceinline__ void mma_f16(float* c, const uint32_t* a,
                                        uint32_t b0, uint32_t b1) {
    asm volatile(
        "mma.sync.aligned.m16n8k16.row.col.f32.f16.f16.f32 "
        "{%0,%1,%2,%3}, {%4,%5,%6,%7}, {%8,%9}, {%0,%1,%2,%3};"
        : "+f"(c[0]), "+f"(c[1]), "+f"(c[2]), "+f"(c[3])
        : "r"(a[0]), "r"(a[1]), "r"(a[2]), "r"(a[3]), "r"(b0), "r"(b1));
}

#define FFT8(x0,x1,x2,x3,x4,x5,x6,x7, R0,R4,R1,I1,R2,I2,R3,I3)                \
    {                                                                         \
        const float cc = 0.70710678118654752440f;                             \
        float s04 = (x0) + (x4), d04 = (x0) - (x4);                           \
        float s26 = (x2) + (x6), d26 = (x2) - (x6);                           \
        float s15 = (x1) + (x5), d15 = (x1) - (x5);                           \
        float s37 = (x3) + (x7), d37 = (x3) - (x7);                           \
        R0 = s04 + s26 + s15 + s37;                                           \
        R4 = s04 + s26 - s15 - s37;                                           \
        R2 = s04 - s26;                                                       \
        I2 = s37 - s15;                                                       \
        float e = cc * (d15 - d37), o = cc * (d15 + d37);                     \
        R1 = d04 + e;  I1 = -d26 - o;                                         \
        R3 = d04 - e;  I3 =  d26 - o;                                         \
    }

// ---------------- Kernel 1: x -> freq planes (fp16) -------------------------
__global__ void fftx_kernel(const float4* __restrict__ x4) {
    int t  = blockIdx.x * blockDim.x + threadIdx.x;  // MDIM*NB
    int m  = t >> 9;
    int ib = t & 511;
    float4 a = x4[(size_t)m * 1024 + ib * 2];
    float4 b = x4[(size_t)m * 1024 + ib * 2 + 1];
    float R0, R4, R1, I1, R2, I2, R3, I3;
    FFT8(a.x, a.y, a.z, a.w, b.x, b.y, b.z, b.w, R0, R4, R1, I1, R2, I2, R3, I3);
    __half* p = g_X + (size_t)m * AK + ib;
    p[0]    = __float2half_rn(R0);
    p[512]  = __float2half_rn(R4);
    p[1024] = __float2half_rn(R1);
    p[1536] = __float2half_rn(I1);
    p[2048] = __float2half_rn(R2);
    p[2560] = __float2half_rn(I2);
    p[3072] = __float2half_rn(R3);
    p[3584] = __float2half_rn(I3);
}

// ---------------- Kernel 2: circ -> freq weights (fp16, irfft-scaled) -------
__global__ void fftc_kernel(const float* __restrict__ circ) {
    int t  = blockIdx.x * blockDim.x + threadIdx.x;  // NB*NB
    int nb = t >> 9;
    int ib = t & 511;
    const float* cp = circ + ((size_t)nb * NB + ib) * 8;
    float R0, R4, R1, I1, R2, I2, R3, I3;
    FFT8(cp[0], cp[1], cp[2], cp[3], cp[4], cp[5], cp[6], cp[7],
         R0, R4, R1, I1, R2, I2, R3, I3);
    // Fold irfft constants: DC/Nyquist x 1/8, AC frequencies x 2/8.
    R0 *= 0.125f; R4 *= 0.125f;
    R1 *= 0.25f;  I1 *= 0.25f;
    R2 *= 0.25f;  I2 *= 0.25f;
    R3 *= 0.25f;  I3 *= 0.25f;
    const size_t JS = (size_t)NB * BK_ROW;
    __half* r = g_B + (size_t)nb * BK_ROW + ib;
    r[0 * JS] = __float2half_rn(R0);
    r[1 * JS] = __float2half_rn(R4);
    r[2 * JS] = __float2half_rn(R1);  r[2 * JS + 512] = __float2half_rn(-I1);
    r[3 * JS] = __float2half_rn(I1);  r[3 * JS + 512] = __float2half_rn( R1);
    r[4 * JS] = __float2half_rn(R2);  r[4 * JS + 512] = __float2half_rn(-I2);
    r[5 * JS] = __float2half_rn(I2);  r[5 * JS + 512] = __float2half_rn( R2);
    r[6 * JS] = __float2half_rn(R3);  r[6 * JS + 512] = __float2half_rn(-I3);
    r[7 * JS] = __float2half_rn(I3);  r[7 * JS + 512] = __float2half_rn( R3);
}

// ---------------- Kernel 3: batched FP16 mma.sync GEMM ----------------------
// 8 jobs x 64 m-tiles x 4 n-tiles. 8 warps as 2(m) x 4(n), warp tile 64x32.
__global__ void __launch_bounds__(THREADS) bc_gemm() {
    extern __shared__ char smem[];
    uint32_t sb0 = smem_u32(smem);
    const int tid = threadIdx.x;
    const int wid = tid >> 5;
    const int lid = tid & 31;
    const int wm = (wid >> 2) * 64;
    const int wn = (wid & 3) * 32;

    const int job = blockIdx.x >> 8;                 // 256 CTAs per job
    const int rem = blockIdx.x & 255;
    const int m0 = (rem & 63) * BM;
    const int n0 = (rem >> 6) * BN;
    const int NKIT = (job < 2) ? 8 : 16;             // K = 512 or 1024, BK=64

    const __half* Arow = g_X + (size_t)m0 * AK + (job >> 1) * 1024
                             + ((job == 1) ? 512 : 0);
    const __half* Brow = g_B + (size_t)job * NB * BK_ROW + (size_t)n0 * BK_ROW;

    auto load_stage = [&](int s, int kiter) {
        uint32_t stg = sb0 + s * STAGE_BYTES;
        int k0 = kiter * BK;
#pragma unroll
        for (int q = 0; q < 4; q++) {
            int idx = tid + q * THREADS;             // 0..1023 chunks of 16B
            int row = idx >> 3;
            int ch  = idx & 7;
            uint32_t sw = SWZ((uint32_t)(row * 128 + ch * 16));
            cp_async16(stg + sw,              Arow + (size_t)row * AK     + k0 + ch * 8);
            cp_async16(stg + TILE_BYTES + sw, Brow + (size_t)row * BK_ROW + k0 + ch * 8);
        }
        cp_commit();
    };

    float acc[4][4][4];
#pragma unroll
    for (int mf = 0; mf < 4; mf++)
#pragma unroll
        for (int nf = 0; nf < 4; nf++)
#pragma unroll
            for (int r = 0; r < 4; r++) acc[mf][nf][r] = 0.0f;

    load_stage(0, 0);
    load_stage(1, 1);

    const int lrow = lid & 15;
    const int lcol = (lid >> 4) * 16;

    for (int i = 0; i < NKIT; i++) {
        cp_wait<1>();
        __syncthreads();
        if (i + 2 < NKIT) load_stage((i + 2) % NSTAGE, i + 2);

        uint32_t Ab = sb0 + (i % NSTAGE) * STAGE_BYTES;
        uint32_t Bb = Ab + TILE_BYTES;

#pragma unroll
        for (int ks = 0; ks < 4; ks++) {             // 4 x k16 = BK 64
            uint32_t a[4][4];
#pragma unroll
            for (int mf = 0; mf < 4; mf++) {
                uint32_t off = (uint32_t)((wm + mf * 16 + lrow) * 128 + ks * 32 + lcol);
                ldsm4(a[mf], Ab + SWZ(off));
            }
            uint32_t b[2][4];
#pragma unroll
            for (int p = 0; p < 2; p++) {
                uint32_t off = (uint32_t)((wn + p * 16 + lrow) * 128 + ks * 32 + lcol);
                ldsm4(b[p], Bb + SWZ(off));
            }
#pragma unroll
            for (int mf = 0; mf < 4; mf++)
#pragma unroll
                for (int nf = 0; nf < 4; nf++) {
                    int p = nf >> 1, o = nf & 1;
                    mma_f16(acc[mf][nf], a[mf], b[p][o], b[p][2 + o]);
                }
        }
    }

    // Epilogue: pack to fp16 planes (half2 stores, coalesced 16B per 4 lanes).
    __half* O = g_O + (size_t)job * PLANE;
    const int crow = lid >> 2;
    const int ccol = 2 * (lid & 3);
#pragma unroll
    for (int nf = 0; nf < 4; nf++) {
        int col = n0 + wn + nf * 8 + ccol;
#pragma unroll
        for (int mf = 0; mf < 4; mf++) {
            int row = m0 + wm + mf * 16 + crow;
            *(__half2*)(O + (size_t)row * NB + col) =
                __floats2half2_rn(acc[mf][nf][0], acc[mf][nf][1]);
            *(__half2*)(O + (size_t)(row + 8) * NB + col) =
                __floats2half2_rn(acc[mf][nf][2], acc[mf][nf][3]);
        }
    }
}

// ---------------- Kernel 4: inverse 8-pt rfft (scales pre-folded) + bias ----
__global__ void ifft_kernel(const float* __restrict__ bias,
                            float* __restrict__ out) {
    int t  = blockIdx.x * blockDim.x + threadIdx.x;  // MDIM*NB
    int m  = t >> 9;
    int nb = t & 511;
    const __half* p = g_O + (size_t)m * NB + nb;
    float R0 = __half2float(p[0 * PLANE]), R4 = __half2float(p[1 * PLANE]);
    float R1 = __half2float(p[2 * PLANE]), I1 = __half2float(p[3 * PLANE]);
    float R2 = __half2float(p[4 * PLANE]), I2 = __half2float(p[5 * PLANE]);
    float R3 = __half2float(p[6 * PLANE]), I3 = __half2float(p[7 * PLANE]);

    const float cc = 0.70710678118654752440f;
    float se = R0 + R4, so = R0 - R4;
    float y0 = se + R1 + R2 + R3;
    float y2 = se - I1 - R2 + I3;
    float y4 = se - R1 + R2 - R3;
    float y6 = se + I1 - R2 - I3;
    float a1 = cc * (R1 - I1), b1 = cc * (R1 + I1);
    float a3 = cc * (R3 - I3), b3 = cc * (R3 + I3);
    float y1 = so + a1 - I2 - b3;
    float y3 = so - b1 + I2 + a3;
    float y5 = so - a1 - I2 + b3;
    float y7 = so + b1 + I2 - a3;

    const float4 bv0 = *(const float4*)(bias + nb * 8);
    const float4 bv1 = *(const float4*)(bias + nb * 8 + 4);
    float4* dst = (float4*)(out + (size_t)m * 4096 + nb * 8);
    dst[0] = make_float4(y0 + bv0.x, y1 + bv0.y, y2 + bv0.z, y3 + bv0.w);
    dst[1] = make_float4(y4 + bv1.x, y5 + bv1.y, y6 + bv1.z, y7 + bv1.w);
}

// ---------------- Launch ----------------------------------------------------

extern "C" void kernel_launch(void* const* d_in, const int* in_sizes, int n_in,
                              void* d_out, int out_size) {
    const float* x    = (const float*)d_in[0];
    const float* circ = (const float*)d_in[1];
    const float* bias = (const float*)d_in[2];
    float* out = (float*)d_out;

    fftx_kernel<<<(MDIM * NB) / 256, 256>>>((const float4*)x);
    fftc_kernel<<<(NB * NB) / 256, 256>>>(circ);

    cudaFuncSetAttribute(bc_gemm, cudaFuncAttributeMaxDynamicSharedMemorySize,
                         SMEM_TOTAL);
    bc_gemm<<<8 * 64 * 4, THREADS, SMEM_TOTAL>>>();   // 2048 CTAs

    ifft_kernel<<<(MDIM * NB) / 256, 256>>>(bias, out);
    (void)in_sizes; (void)n_in; (void)out_size;
}

// round 12
// speedup vs baseline: 1.9804x; 1.0891x over previous
#include <cuda_runtime.h>
#include <cuda_fp16.h>
#include <cstdint>
#include <cstddef>

// ----------------------------------------------------------------------------
// BlockCirculantLinear on GB300 (sm_103a; PTX target lacks 'a' => no tcgen05).
// FFT-domain formulation, fp16 mma.sync m16n8k16.
// R8: Gauss 3-mult complex multiply per AC frequency: 11 uniform K=512 GEMM
// jobs (vs 14 units) => 21% fewer HMMA. Plane recombination folded into ifft.
// half2-vectorized fftx/ifft transforms.
//   A planes (g_X, 11 x 512): 0:X0 1:X4 2:X1r 3:X1i 4:X1s 5:X2r 6:X2i 7:X2s
//                             8:X3r 9:X3i 10:X3s        (Xs = Xr + Xi)
//   B jobs   (g_B, 11 x [512n x 512k]): same order, C-side, irfft scales folded
//   Output planes (g_O): job j -> plane j; ifft: Rf = P1-P2, If = P3-P1-P2.
// ----------------------------------------------------------------------------

#define BM 128
#define BN 128
#define BK 64
#define NSTAGE 3
#define MDIM 8192
#define NB 512
#define THREADS 256
#define NJOBS 11

static constexpr int AK      = NJOBS * 512;          // 5632, g_X row stride
static constexpr int BK_ROW  = 512;                  // g_B row stride
static constexpr size_t PLANE = (size_t)MDIM * NB;

static constexpr int TILE_BYTES  = BM * BK * 2;          // 16384 (fp16)
static constexpr int STAGE_BYTES = 2 * TILE_BYTES;       // 32768
static constexpr int SMEM_TOTAL  = NSTAGE * STAGE_BYTES; // 98304 -> 2 CTAs/SM

__device__ __half g_X[(size_t)MDIM * AK];              // freq x (fp16), 92MB
__device__ __half g_B[(size_t)NJOBS * NB * BK_ROW];    // freq weights (fp16)
__device__ __half g_O[(size_t)NJOBS * PLANE];          // freq planes (fp16)

// ---------------- helpers ---------------------------------------------------

__device__ __forceinline__ uint32_t smem_u32(const void* p) {
    uint32_t a;
    asm("{ .reg .u64 t; cvta.to.shared.u64 t, %1; cvt.u32.u64 %0, t; }"
        : "=r"(a) : "l"(p));
    return a;
}

#define SWZ(off) ((off) ^ (((off) >> 3) & 0x70))

__device__ __forceinline__ void cp_async16(uint32_t dst, const void* src) {
    asm volatile("cp.async.cg.shared.global [%0], [%1], 16;" :: "r"(dst), "l"(src));
}
__device__ __forceinline__ void cp_commit() {
    asm volatile("cp.async.commit_group;" ::: "memory");
}
template <int N> __device__ __forceinline__ void cp_wait() {
    asm volatile("cp.async.wait_group %0;" :: "n"(N) : "memory");
}

__device__ __forceinline__ void ldsm4(uint32_t* r, uint32_t addr) {
    asm volatile("ldmatrix.sync.aligned.m8n8.x4.shared.b16 {%0,%1,%2,%3}, [%4];"
                 : "=r"(r[0]), "=r"(r[1]), "=r"(r[2]), "=r"(r[3]) : "r"(addr));
}

__device__ __forceinline__ void mma_f16(float* c, const uint32_t* a,
                                        uint32_t b0, uint32_t b1) {
    asm volatile(
        "mma.sync.aligned.m16n8k16.row.col.f32.f16.f16.f32 "
        "{%0,%1,%2,%3}, {%4,%5,%6,%7}, {%8,%9}, {%0,%1,%2,%3};"
        : "+f"(c[0]), "+f"(c[1]), "+f"(c[2]), "+f"(c[3])
        : "r"(a[0]), "r"(a[1]), "r"(a[2]), "r"(a[3]), "r"(b0), "r"(b1));
}

#define FFT8(x0,x1,x2,x3,x4,x5,x6,x7, R0,R4,R1,I1,R2,I2,R3,I3)                \
    {                                                                         \
        const float cc = 0.70710678118654752440f;                             \
        float s04 = (x0) + (x4), d04 = (x0) - (x4);                           \
        float s26 = (x2) + (x6), d26 = (x2) - (x6);                           \
        float s15 = (x1) + (x5), d15 = (x1) - (x5);                           \
        float s37 = (x3) + (x7), d37 = (x3) - (x7);                           \
        R0 = s04 + s26 + s15 + s37;                                           \
        R4 = s04 + s26 - s15 - s37;                                           \
        R2 = s04 - s26;                                                       \
        I2 = s37 - s15;                                                       \
        float e = cc * (d15 - d37), o = cc * (d15 + d37);                     \
        R1 = d04 + e;  I1 = -d26 - o;                                         \
        R3 = d04 - e;  I3 =  d26 - o;                                         \
    }

// ---------------- Kernel 1: x -> 11 freq planes (fp16, half2 stores) --------
__global__ void fftx_kernel(const float4* __restrict__ x4) {
    int t  = blockIdx.x * blockDim.x + threadIdx.x;  // MDIM*NB/2
    int m  = t >> 8;
    int ib = (t & 255) * 2;
    float4 a0 = x4[(size_t)m * 1024 + ib * 2];
    float4 b0 = x4[(size_t)m * 1024 + ib * 2 + 1];
    float4 a1 = x4[(size_t)m * 1024 + ib * 2 + 2];
    float4 b1 = x4[(size_t)m * 1024 + ib * 2 + 3];
    float v[2][11];
    {
        float R0, R4, R1, I1, R2, I2, R3, I3;
        FFT8(a0.x, a0.y, a0.z, a0.w, b0.x, b0.y, b0.z, b0.w,
             R0, R4, R1, I1, R2, I2, R3, I3);
        v[0][0] = R0;  v[0][1] = R4;
        v[0][2] = R1;  v[0][3] = I1;  v[0][4]  = R1 + I1;
        v[0][5] = R2;  v[0][6] = I2;  v[0][7]  = R2 + I2;
        v[0][8] = R3;  v[0][9] = I3;  v[0][10] = R3 + I3;
    }
    {
        float R0, R4, R1, I1, R2, I2, R3, I3;
        FFT8(a1.x, a1.y, a1.z, a1.w, b1.x, b1.y, b1.z, b1.w,
             R0, R4, R1, I1, R2, I2, R3, I3);
        v[1][0] = R0;  v[1][1] = R4;
        v[1][2] = R1;  v[1][3] = I1;  v[1][4]  = R1 + I1;
        v[1][5] = R2;  v[1][6] = I2;  v[1][7]  = R2 + I2;
        v[1][8] = R3;  v[1][9] = I3;  v[1][10] = R3 + I3;
    }
    __half* p = g_X + (size_t)m * AK + ib;
#pragma unroll
    for (int pl = 0; pl < 11; pl++)
        *(__half2*)(p + pl * 512) = __floats2half2_rn(v[0][pl], v[1][pl]);
}

// ---------------- Kernel 2: circ -> 11 freq weight matrices (scaled) --------
__global__ void fftc_kernel(const float* __restrict__ circ) {
    int t  = blockIdx.x * blockDim.x + threadIdx.x;  // NB*NB
    int nb = t >> 9;
    int ib = t & 511;
    const float* cp = circ + ((size_t)nb * NB + ib) * 8;
    float R0, R4, R1, I1, R2, I2, R3, I3;
    FFT8(cp[0], cp[1], cp[2], cp[3], cp[4], cp[5], cp[6], cp[7],
         R0, R4, R1, I1, R2, I2, R3, I3);
    // Fold irfft constants: DC/Nyquist x 1/8, AC x 2/8 (applied to all of
    // Cr, Ci, Cs so Re/Im recombination stays linear).
    float w[11];
    w[0] = R0 * 0.125f;  w[1] = R4 * 0.125f;
    w[2] = R1 * 0.25f;   w[3] = I1 * 0.25f;   w[4]  = (R1 + I1) * 0.25f;
    w[5] = R2 * 0.25f;   w[6] = I2 * 0.25f;   w[7]  = (R2 + I2) * 0.25f;
    w[8] = R3 * 0.25f;   w[9] = I3 * 0.25f;   w[10] = (R3 + I3) * 0.25f;
    const size_t JS = (size_t)NB * BK_ROW;
    __half* r = g_B + (size_t)nb * BK_ROW + ib;
#pragma unroll
    for (int j = 0; j < 11; j++) r[j * JS] = __float2half_rn(w[j]);
}

// ---------------- Kernel 3: batched FP16 mma.sync GEMM ----------------------
// 11 jobs x 64 m-tiles x 4 n-tiles, all K=512 (NKIT=8).
__global__ void __launch_bounds__(THREADS) bc_gemm() {
    extern __shared__ char smem[];
    uint32_t sb0 = smem_u32(smem);
    const int tid = threadIdx.x;
    const int wid = tid >> 5;
    const int lid = tid & 31;
    const int wm = (wid >> 2) * 64;
    const int wn = (wid & 3) * 32;

    const int job = blockIdx.x >> 8;                 // 256 CTAs per job
    const int rem = blockIdx.x & 255;
    const int m0 = (rem & 63) * BM;
    const int n0 = (rem >> 6) * BN;
    const int NKIT = 8;                              // K = 512, BK = 64

    const __half* Arow = g_X + (size_t)m0 * AK + job * 512;
    const __half* Brow = g_B + (size_t)job * NB * BK_ROW + (size_t)n0 * BK_ROW;

    auto load_stage = [&](int s, int kiter) {
        uint32_t stg = sb0 + s * STAGE_BYTES;
        int k0 = kiter * BK;
#pragma unroll
        for (int q = 0; q < 4; q++) {
            int idx = tid + q * THREADS;             // 0..1023 chunks of 16B
            int row = idx >> 3;
            int ch  = idx & 7;
            uint32_t sw = SWZ((uint32_t)(row * 128 + ch * 16));
            cp_async16(stg + sw,              Arow + (size_t)row * AK     + k0 + ch * 8);
            cp_async16(stg + TILE_BYTES + sw, Brow + (size_t)row * BK_ROW + k0 + ch * 8);
        }
        cp_commit();
    };

    float acc[4][4][4];
#pragma unroll
    for (int mf = 0; mf < 4; mf++)
#pragma unroll
        for (int nf = 0; nf < 4; nf++)
#pragma unroll
            for (int r = 0; r < 4; r++) acc[mf][nf][r] = 0.0f;

    load_stage(0, 0);
    load_stage(1, 1);

    const int lrow = lid & 15;
    const int lcol = (lid >> 4) * 16;

    for (int i = 0; i < NKIT; i++) {
        cp_wait<1>();
        __syncthreads();
        if (i + 2 < NKIT) load_stage((i + 2) % NSTAGE, i + 2);

        uint32_t Ab = sb0 + (i % NSTAGE) * STAGE_BYTES;
        uint32_t Bb = Ab + TILE_BYTES;

#pragma unroll
        for (int ks = 0; ks < 4; ks++) {             // 4 x k16 = BK 64
            uint32_t a[4][4];
#pragma unroll
            for (int mf = 0; mf < 4; mf++) {
                uint32_t off = (uint32_t)((wm + mf * 16 + lrow) * 128 + ks * 32 + lcol);
                ldsm4(a[mf], Ab + SWZ(off));
            }
            uint32_t b[2][4];
#pragma unroll
            for (int p = 0; p < 2; p++) {
                uint32_t off = (uint32_t)((wn + p * 16 + lrow) * 128 + ks * 32 + lcol);
                ldsm4(b[p], Bb + SWZ(off));
            }
#pragma unroll
            for (int mf = 0; mf < 4; mf++)
#pragma unroll
                for (int nf = 0; nf < 4; nf++) {
                    int p = nf >> 1, o = nf & 1;
                    mma_f16(acc[mf][nf], a[mf], b[p][o], b[p][2 + o]);
                }
        }
    }

    __half* O = g_O + (size_t)job * PLANE;
    const int crow = lid >> 2;
    const int ccol = 2 * (lid & 3);
#pragma unroll
    for (int nf = 0; nf < 4; nf++) {
        int col = n0 + wn + nf * 8 + ccol;
#pragma unroll
        for (int mf = 0; mf < 4; mf++) {
            int row = m0 + wm + mf * 16 + crow;
            *(__half2*)(O + (size_t)row * NB + col) =
                __floats2half2_rn(acc[mf][nf][0], acc[mf][nf][1]);
            *(__half2*)(O + (size_t)(row + 8) * NB + col) =
                __floats2half2_rn(acc[mf][nf][2], acc[mf][nf][3]);
        }
    }
}

// ---------------- Kernel 4: Gauss recombine + inverse rfft + bias (half2) ---
__global__ void ifft_kernel(const float* __restrict__ bias,
                            float* __restrict__ out) {
    int t  = blockIdx.x * blockDim.x + threadIdx.x;  // MDIM*NB/2
    int m  = t >> 8;
    int nb = (t & 255) * 2;
    const __half* p = g_O + (size_t)m * NB + nb;
    float2 q[11];
#pragma unroll
    for (int j = 0; j < 11; j++)
        q[j] = __half22float2(*(const __half2*)(p + j * PLANE));

    const float cc = 0.70710678118654752440f;
#pragma unroll
    for (int h = 0; h < 2; h++) {
        float R0 = h ? q[0].y : q[0].x, R4 = h ? q[1].y : q[1].x;
        float P1, P2, P3;
        P1 = h ? q[2].y : q[2].x;  P2 = h ? q[3].y : q[3].x;  P3 = h ? q[4].y : q[4].x;
        float R1 = P1 - P2, I1 = P3 - P1 - P2;
        P1 = h ? q[5].y : q[5].x;  P2 = h ? q[6].y : q[6].x;  P3 = h ? q[7].y : q[7].x;
        float R2 = P1 - P2, I2 = P3 - P1 - P2;
        P1 = h ? q[8].y : q[8].x;  P2 = h ? q[9].y : q[9].x;  P3 = h ? q[10].y : q[10].x;
        float R3 = P1 - P2, I3 = P3 - P1 - P2;

        float se = R0 + R4, so = R0 - R4;
        float y0 = se + R1 + R2 + R3;
        float y2 = se - I1 - R2 + I3;
        float y4 = se - R1 + R2 - R3;
        float y6 = se + I1 - R2 - I3;
        float a1 = cc * (R1 - I1), b1 = cc * (R1 + I1);
        float a3 = cc * (R3 - I3), b3 = cc * (R3 + I3);
        float y1 = so + a1 - I2 - b3;
        float y3 = so - b1 + I2 + a3;
        float y5 = so - a1 - I2 + b3;
        float y7 = so + b1 + I2 - a3;

        int nbh = nb + h;
        const float4 bv0 = *(const float4*)(bias + nbh * 8);
        const float4 bv1 = *(const float4*)(bias + nbh * 8 + 4);
        float4* dst = (float4*)(out + (size_t)m * 4096 + nbh * 8);
        dst[0] = make_float4(y0 + bv0.x, y1 + bv0.y, y2 + bv0.z, y3 + bv0.w);
        dst[1] = make_float4(y4 + bv1.x, y5 + bv1.y, y6 + bv1.z, y7 + bv1.w);
    }
}

// ---------------- Launch ----------------------------------------------------

extern "C" void kernel_launch(void* const* d_in, const int* in_sizes, int n_in,
                              void* d_out, int out_size) {
    const float* x    = (const float*)d_in[0];
    const float* circ = (const float*)d_in[1];
    const float* bias = (const float*)d_in[2];
    float* out = (float*)d_out;

    fftx_kernel<<<(MDIM * NB / 2) / 256, 256>>>((const float4*)x);
    fftc_kernel<<<(NB * NB) / 256, 256>>>(circ);

    cudaFuncSetAttribute(bc_gemm, cudaFuncAttributeMaxDynamicSharedMemorySize,
                         SMEM_TOTAL);
    bc_gemm<<<NJOBS * 64 * 4, THREADS, SMEM_TOTAL>>>();   // 2816 CTAs

    ifft_kernel<<<(MDIM * NB / 2) / 256, 256>>>(bias, out);
    (void)in_sizes; (void)n_in; (void)out_size;
}